// round 16
// baseline (speedup 1.0000x reference)
#include <cuda_runtime.h>
#include <cuda_fp16.h>
#include <cstdint>
#include <math.h>

#define CDIM 512
#define NPOS 16384   // T*H*W
#define NELEM (CDIM*NPOS)

// ------------------------- scratch (device globals) -------------------------
__device__ __half g_X1[NELEM];            // fp16 residual carrier [c,n] after spatial
__device__ __half g_S [16*1024*1024];     // fp16 scores
__device__ __half g_H  [NELEM];           // rms output [n,c]
__device__ __half g_QKV[NPOS*1536];       // spatial QK (ld 1024) / temporal QKV (ld 1536)
__device__ __half g_V [NELEM];            // spatial V [c,n]
__device__ __half g_O [NELEM];            // attention out [n,c]
__device__ __half g_P [16*1024*1024];     // fp16 attention probs
__device__ __half g_W [8*CDIM*CDIM];      // fp16 weights (qs ks vs ps qt kt vt pt)
__device__ float  g_BC[4096];             // packed biases

// ------------------------- helpers -------------------------
__device__ __forceinline__ uint32_t smem_u32(const void* p){
    uint32_t a;
    asm("{ .reg .u64 t; cvta.to.shared.u64 t, %1; cvt.u32.u64 %0, t; }" : "=r"(a) : "l"(p));
    return a;
}
#define CP_ASYNC16(dst_u32, src_ptr) \
    asm volatile("cp.async.cg.shared.global [%0], [%1], 16;" :: "r"(dst_u32), "l"(src_ptr))
#define CP_COMMIT() asm volatile("cp.async.commit_group;" ::: "memory")
#define CP_WAIT0()  asm volatile("cp.async.wait_group 0;" ::: "memory")
#define CP_WAIT1()  asm volatile("cp.async.wait_group 1;" ::: "memory")

__device__ __forceinline__ void mma_f16(float* d, const uint32_t* a, const uint32_t* b){
    asm volatile(
        "mma.sync.aligned.m16n8k16.row.col.f32.f16.f16.f32 "
        "{%0,%1,%2,%3}, {%4,%5,%6,%7}, {%8,%9}, {%0,%1,%2,%3};"
        : "+f"(d[0]), "+f"(d[1]), "+f"(d[2]), "+f"(d[3])
        : "r"(a[0]), "r"(a[1]), "r"(a[2]), "r"(a[3]), "r"(b[0]), "r"(b[1]));
}
__device__ __forceinline__ void ldm_x4(uint32_t* r, uint32_t addr){
    asm volatile("ldmatrix.sync.aligned.m8n8.x4.shared.b16 {%0,%1,%2,%3}, [%4];"
        : "=r"(r[0]), "=r"(r[1]), "=r"(r[2]), "=r"(r[3]) : "r"(addr));
}

// ---------------------------------------------------------------------------
// fp16 mma.sync GEMM (best config), both operands K-major:
//   C[z*czs + (y*128+r)*ldc + x*128 + s] =
//     scale * sum_k A[...] * B[...]  (+ bias[row or col])  (+ Res)
// OUTH: write fp16 (else fp32). RESM: 0 none, 1 fp32 residual, 2 fp16 residual.
// Block 128x128, BK=64, 256 threads (2x4 warps), 3-stage cp.async, 2 CTAs/SM.
// ---------------------------------------------------------------------------
#define BK     64
#define ROWB   144                   // 64 halfs (128B) + 16B pad
#define STAGEB (128*ROWB*2)          // A+B per stage = 36864 B
#define GDSMEM (STAGEB*3)            // 110592 B

template<bool OUTH, int RESM>
__global__ void __launch_bounds__(256, 2)
gemm_h(const __half* __restrict__ A, long lda, long azs,
       const __half* __restrict__ B, long ldb, long bzs,
       void* __restrict__ Cp, long ldc, long czs,
       const float* __restrict__ bias, int biasRow,
       const void* __restrict__ Res,
       int Kdim, float scale)
{
    extern __shared__ char sm[];
    const int tid  = threadIdx.x;
    const int wid  = tid >> 5;
    const int lane = tid & 31;
    const int wm   = wid >> 2;   // 0..1 (m half: 64 rows)
    const int wn   = wid & 3;    // 0..3 (n quarter: 32 cols)

    const long mRow0 = (long)blockIdx.y * 128;
    const long nCol0 = (long)blockIdx.x * 128;
    const __half* Ag = A + (long)blockIdx.z * azs + mRow0 * lda;
    const __half* Bg = B + (long)blockIdx.z * bzs + nCol0 * ldb;

    const uint32_t sbase = smem_u32(sm);
    const int lrow = tid >> 3;        // 0..31
    const int loct = tid & 7;         // 16B octant within 128B row

    const uint32_t lmOff = (uint32_t)(lane & 15) * ROWB + (uint32_t)(lane >> 4) * 16;

    float acc[4][4][4];
    #pragma unroll
    for (int i = 0; i < 4; i++)
        #pragma unroll
        for (int j = 0; j < 4; j++)
            #pragma unroll
            for (int q = 0; q < 4; q++) acc[i][j][q] = 0.f;

    const int NC = Kdim >> 6;   // BK = 64

    #define LOADC(cc, st) do {                                                    \
        const long k0 = (long)(cc) * BK;                                          \
        uint32_t dA = sbase + (st)*STAGEB;                                        \
        uint32_t dB = dA + 128*ROWB;                                              \
        _Pragma("unroll")                                                         \
        for (int i = 0; i < 4; i++) {                                             \
            int row = lrow + i*32;                                                \
            CP_ASYNC16(dA + row*ROWB + loct*16, Ag + (long)row*lda + k0 + loct*8);\
            CP_ASYNC16(dB + row*ROWB + loct*16, Bg + (long)row*ldb + k0 + loct*8);\
        }                                                                         \
        CP_COMMIT();                                                               \
    } while(0)

    LOADC(0, 0); LOADC(1, 1);

    int st = 0;
    for (int c = 0; c < NC; ++c) {
        if (c + 1 < NC) CP_WAIT1(); else CP_WAIT0();
        __syncthreads();
        if (c + 2 < NC) {
            int st2 = st + 2; if (st2 >= 3) st2 -= 3;
            LOADC(c + 2, st2);
        }

        const uint32_t stB = sbase + st*STAGEB;
        const uint32_t aAddr = stB + (uint32_t)(wm*64)*ROWB + lmOff;
        const uint32_t bAddr = stB + 128*ROWB + (uint32_t)(wn*32)*ROWB + lmOff;

        #pragma unroll
        for (int ks = 0; ks < 4; ks++) {
            const uint32_t kOff = ks*32;
            uint32_t af[4][4];
            #pragma unroll
            for (int mi = 0; mi < 4; mi++)
                ldm_x4(af[mi], aAddr + mi*(16*ROWB) + kOff);
            uint32_t bf[4][2];
            #pragma unroll
            for (int g = 0; g < 2; g++) {
                uint32_t bq4[4];
                ldm_x4(bq4, bAddr + g*(16*ROWB) + kOff);
                bf[2*g+0][0] = bq4[0]; bf[2*g+1][0] = bq4[1];
                bf[2*g+0][1] = bq4[2]; bf[2*g+1][1] = bq4[3];
            }
            #pragma unroll
            for (int mi = 0; mi < 4; mi++)
                #pragma unroll
                for (int ni = 0; ni < 4; ni++)
                    mma_f16(acc[mi][ni], af[mi], bf[ni]);
        }

        if (++st == 3) st = 0;
    }

    // ---- epilogue ----
    const long rBase = mRow0 + wm*64 + (lane >> 2);
    const long cBase = nCol0 + wn*32 + (lane & 3) * 2;
    #pragma unroll
    for (int mi = 0; mi < 4; mi++) {
        #pragma unroll
        for (int half_ = 0; half_ < 2; half_++) {
            const long r = rBase + mi*16 + half_*8;
            const float bvr = (bias && biasRow) ? __ldg(bias + r) : 0.f;
            const long rowOff = (long)blockIdx.z * czs + r * ldc;
            #pragma unroll
            for (int ni = 0; ni < 4; ni++) {
                const long cc = cBase + ni*8;
                float v0 = acc[mi][ni][half_*2 + 0] * scale;
                float v1 = acc[mi][ni][half_*2 + 1] * scale;
                if (bias) {
                    if (biasRow) { v0 += bvr; v1 += bvr; }
                    else { v0 += __ldg(bias + cc); v1 += __ldg(bias + cc + 1); }
                }
                if (RESM == 1) {
                    float2 rv = *reinterpret_cast<const float2*>(
                        (const float*)Res + rowOff + cc);
                    v0 += rv.x; v1 += rv.y;
                } else if (RESM == 2) {
                    __half2 rh = *reinterpret_cast<const __half2*>(
                        (const __half*)Res + rowOff + cc);
                    float2 rf = __half22float2(rh);
                    v0 += rf.x; v1 += rf.y;
                }
                if (OUTH) {
                    __half2 h = __floats2half2_rn(v0, v1);
                    *reinterpret_cast<__half2*>((__half*)Cp + rowOff + cc) = h;
                } else {
                    float2 o; o.x = v0; o.y = v1;
                    *reinterpret_cast<float2*>((float*)Cp + rowOff + cc) = o;
                }
            }
        }
    }
    #undef LOADC
}

// ---------------------------------------------------------------------------
// Weight fp32->fp16 conversion + bias packing
// ---------------------------------------------------------------------------
__global__ void convw(const float* __restrict__ w0, const float* __restrict__ w1,
                      const float* __restrict__ w2, const float* __restrict__ w3,
                      const float* __restrict__ w4, const float* __restrict__ w5,
                      const float* __restrict__ w6, const float* __restrict__ w7,
                      const float* __restrict__ qsb, const float* __restrict__ ksb,
                      const float* __restrict__ qtb, const float* __restrict__ ktb,
                      const float* __restrict__ vtb,
                      __half* __restrict__ W, float* __restrict__ BC)
{
    long i = (long)blockIdx.x * 256 + threadIdx.x;
    int sel = (int)(i >> 18);
    long off = i & 262143;
    const float* src;
    switch (sel) {
        case 0: src = w0; break; case 1: src = w1; break;
        case 2: src = w2; break; case 3: src = w3; break;
        case 4: src = w4; break; case 5: src = w5; break;
        case 6: src = w6; break; default: src = w7; break;
    }
    W[i] = __float2half_rn(src[off]);
    if (i < 2560) {
        long j = i;
        if      (j < 512)  BC[j]               = qsb[j];
        else if (j < 1024) BC[j]               = ksb[j - 512];
        else if (j < 1536) BC[2048 + (j-1024)] = qtb[j - 1024];
        else if (j < 2048) BC[2560 + (j-1536)] = ktb[j - 1536];
        else               BC[3072 + (j-2048)] = vtb[j - 2048];
    }
}

// ---------------------------------------------------------------------------
// Fused transpose + RMS: X [c,n] (fp32 or fp16) -> H [n,c] fp16
// Handles positions [nbase + blockIdx.x*32, +32).
// ---------------------------------------------------------------------------
#define TRMS_SMEM (512*33*4)
template<typename TI>
__global__ void __launch_bounds__(256)
trms(const TI* __restrict__ X, __half* __restrict__ H,
     const float* __restrict__ gamma, int nbase)
{
    extern __shared__ float ts[];   // [512][33]
    __shared__ float red[8][32];
    __shared__ float invs[32];
    const int n0 = nbase + blockIdx.x * 32;
    const int tid = threadIdx.x;

    if (sizeof(TI) == 4) {
        for (int idx = tid; idx < 4096; idx += 256) {
            int c = idx >> 3, q = idx & 7;
            float4 v = *reinterpret_cast<const float4*>((const float*)X + (long)c*NPOS + n0 + q*4);
            float* row = ts + c*33 + q*4;
            row[0]=v.x; row[1]=v.y; row[2]=v.z; row[3]=v.w;
        }
    } else {
        for (int idx = tid; idx < 2048; idx += 256) {
            int c = idx >> 2, q = idx & 3;
            uint4 u = *reinterpret_cast<const uint4*>((const __half*)X + (long)c*NPOS + n0 + q*8);
            const __half* hp = reinterpret_cast<const __half*>(&u);
            float* row = ts + c*33 + q*8;
            #pragma unroll
            for (int j = 0; j < 8; j++) row[j] = __half2float(hp[j]);
        }
    }
    __syncthreads();
    {
        int col = tid & 31, seg = tid >> 5;
        float ss = 0.f;
        #pragma unroll 8
        for (int c = seg*64; c < seg*64 + 64; c++) {
            float v = ts[c*33 + col]; ss += v*v;
        }
        red[seg][col] = ss;
    }
    __syncthreads();
    if (tid < 32) {
        float ss = 0.f;
        #pragma unroll
        for (int s = 0; s < 8; s++) ss += red[s][tid];
        invs[tid] = 22.62741699796952f / fmaxf(sqrtf(ss), 1e-12f);
    }
    __syncthreads();
    for (int idx = tid; idx < 16384; idx += 256) {
        int nl = idx >> 9, c = idx & 511;
        float v = ts[c*33 + nl];
        H[(long)(n0 + nl) * 512 + c] = __float2half_rn(v * invs[nl] * gamma[c]);
    }
}

// ---------------------------------------------------------------------------
// Softmax over 1024-long fp16 rows -> fp16 probs
// ---------------------------------------------------------------------------
__global__ void softmax1024h(const __half* __restrict__ S, __half* __restrict__ P)
{
    size_t row = blockIdx.x;
    const uint2* p = reinterpret_cast<const uint2*>(S + row * 1024);
    int tid = threadIdx.x;
    uint2 u = p[tid];
    float2 a = __half22float2(*reinterpret_cast<__half2*>(&u.x));
    float2 b = __half22float2(*reinterpret_cast<__half2*>(&u.y));
    float4 v; v.x = a.x; v.y = a.y; v.z = b.x; v.w = b.y;

    __shared__ float redm[8];
    __shared__ float reds[8];

    float mx = fmaxf(fmaxf(v.x, v.y), fmaxf(v.z, v.w));
    #pragma unroll
    for (int o = 16; o; o >>= 1) mx = fmaxf(mx, __shfl_xor_sync(0xffffffffu, mx, o));
    if ((tid & 31) == 0) redm[tid >> 5] = mx;
    __syncthreads();
    mx = redm[0];
    #pragma unroll
    for (int i = 1; i < 8; i++) mx = fmaxf(mx, redm[i]);

    v.x = __expf(v.x - mx); v.y = __expf(v.y - mx);
    v.z = __expf(v.z - mx); v.w = __expf(v.w - mx);

    float sm = v.x + v.y + v.z + v.w;
    #pragma unroll
    for (int o = 16; o; o >>= 1) sm += __shfl_xor_sync(0xffffffffu, sm, o);
    if ((tid & 31) == 0) reds[tid >> 5] = sm;
    __syncthreads();
    sm = 0.f;
    #pragma unroll
    for (int i = 0; i < 8; i++) sm += reds[i];

    float r = 1.f / sm;
    __half2 h0 = __floats2half2_rn(v.x * r, v.y * r);
    __half2 h1 = __floats2half2_rn(v.z * r, v.w * r);
    __half2* dst = reinterpret_cast<__half2*>(P + row * 1024 + tid * 4);
    dst[0] = h0; dst[1] = h1;
}

// ---------------------------------------------------------------------------
// Temporal attention: QKV packed [NPOS, 1536] fp16 (Q +0, K +512, V +1024).
// Block = one hw (hw0 + blockIdx.x), 128 threads. O out [NPOS, 512] fp16.
// ---------------------------------------------------------------------------
__global__ void __launch_bounds__(128)
temporal_t(const __half* __restrict__ QKV, __half* __restrict__ Ot,
           const int* __restrict__ winp, int hw0)
{
    __shared__ float kv[16][512];
    __shared__ float at[16][16];
    const int hw = hw0 + blockIdx.x;
    const int tid = threadIdx.x;
    const int wid = tid >> 5, lane = tid & 31;
    const float scale = 0.04419417382415922f;

    for (int idx = tid; idx < 4096; idx += 128) {
        int t = idx >> 8, c2 = idx & 255;
        __half2 h = *reinterpret_cast<const __half2*>(QKV + ((long)(t*1024 + hw))*1536 + 512 + c2*2);
        float2 f = __half22float2(h);
        kv[t][c2*2] = f.x; kv[t][c2*2+1] = f.y;
    }
    __syncthreads();

    #pragma unroll
    for (int ii = 0; ii < 4; ii++) {
        int i = wid + ii*4;
        float qv[16];
        const __half* qr = QKV + ((long)(i*1024 + hw)) * 1536;
        #pragma unroll
        for (int u = 0; u < 16; u++) qv[u] = __half2float(qr[lane + 32*u]);
        #pragma unroll
        for (int j = 0; j < 16; j++) {
            float s = 0.f;
            #pragma unroll
            for (int u = 0; u < 16; u++) s += qv[u] * kv[j][lane + 32*u];
            #pragma unroll
            for (int o = 16; o; o >>= 1) s += __shfl_xor_sync(0xffffffffu, s, o);
            if (lane == 0) at[i][j] = s * scale;
        }
    }
    __syncthreads();

    int win = winp ? *winp : 8;
    if (tid < 16) {
        int i = tid;
        float mx = -3.0e38f;
        #pragma unroll
        for (int j = 0; j < 16; j++) {
            bool ok = (j <= i) && (win <= 0 || (i - j) < win);
            if (ok) mx = fmaxf(mx, at[i][j]);
        }
        float sum = 0.f, e[16];
        #pragma unroll
        for (int j = 0; j < 16; j++) {
            bool ok = (j <= i) && (win <= 0 || (i - j) < win);
            e[j] = ok ? __expf(at[i][j] - mx) : 0.f;
            sum += e[j];
        }
        float rinv = 1.f / sum;
        #pragma unroll
        for (int j = 0; j < 16; j++) at[i][j] = e[j] * rinv;
    }
    __syncthreads();

    for (int idx = tid; idx < 4096; idx += 128) {
        int t = idx >> 8, c2 = idx & 255;
        __half2 h = *reinterpret_cast<const __half2*>(QKV + ((long)(t*1024 + hw))*1536 + 1024 + c2*2);
        float2 f = __half22float2(h);
        kv[t][c2*2] = f.x; kv[t][c2*2+1] = f.y;
    }
    __syncthreads();

    #pragma unroll
    for (int ii = 0; ii < 4; ii++) {
        int i = wid + ii*4;
        float a[16];
        #pragma unroll
        for (int j = 0; j < 16; j++) a[j] = at[i][j];
        __half* orow = Ot + ((long)(i*1024 + hw)) * 512;
        #pragma unroll
        for (int u = 0; u < 16; u++) {
            float o = 0.f;
            #pragma unroll
            for (int j = 0; j < 16; j++) o += a[j] * kv[j][lane + 32*u];
            orow[lane + 32*u] = __float2half_rn(o);
        }
    }
}

// ---------------------------------------------------------------------------
extern "C" void kernel_launch(void* const* d_in, const int* in_sizes, int n_in,
                              void* d_out, int out_size)
{
    const float* x     = (const float*)d_in[0];
    const float* qs_w  = (const float*)d_in[1];
    const float* qs_b  = (const float*)d_in[2];
    const float* ks_w  = (const float*)d_in[3];
    const float* ks_b  = (const float*)d_in[4];
    const float* vs_w  = (const float*)d_in[5];
    const float* vs_b  = (const float*)d_in[6];
    const float* ps_w  = (const float*)d_in[7];
    const float* ps_b  = (const float*)d_in[8];
    const float* qt_w  = (const float*)d_in[9];
    const float* qt_b  = (const float*)d_in[10];
    const float* kt_w  = (const float*)d_in[11];
    const float* kt_b  = (const float*)d_in[12];
    const float* vt_w  = (const float*)d_in[13];
    const float* vt_b  = (const float*)d_in[14];
    const float* pt_w  = (const float*)d_in[15];
    const float* pt_b  = (const float*)d_in[16];
    const float* gm_s  = (const float*)d_in[17];
    const float* gm_t  = (const float*)d_in[18];
    const int*   winp  = (n_in > 19) ? (const int*)d_in[19] : nullptr;
    float* out = (float*)d_out;

    float *BC;
    __half *X1, *S, *H, *QKV, *V, *O, *P, *W;
    cudaGetSymbolAddress((void**)&X1,  g_X1);
    cudaGetSymbolAddress((void**)&S,   g_S);
    cudaGetSymbolAddress((void**)&BC,  g_BC);
    cudaGetSymbolAddress((void**)&H,   g_H);
    cudaGetSymbolAddress((void**)&QKV, g_QKV);
    cudaGetSymbolAddress((void**)&V,   g_V);
    cudaGetSymbolAddress((void**)&O,   g_O);
    cudaGetSymbolAddress((void**)&P,   g_P);
    cudaGetSymbolAddress((void**)&W,   g_W);

    static int attr_set = 0;
    static cudaStream_t s1;
    static cudaEvent_t evFork, evW, evH, evQK, evV, evQ1, evQ2, evEnd;
    if (!attr_set) {
        cudaFuncSetAttribute(gemm_h<true,0>,  cudaFuncAttributeMaxDynamicSharedMemorySize, GDSMEM);
        cudaFuncSetAttribute(gemm_h<true,1>,  cudaFuncAttributeMaxDynamicSharedMemorySize, GDSMEM);
        cudaFuncSetAttribute(gemm_h<false,2>, cudaFuncAttributeMaxDynamicSharedMemorySize, GDSMEM);
        cudaFuncSetAttribute(trms<float>,  cudaFuncAttributeMaxDynamicSharedMemorySize, TRMS_SMEM);
        cudaFuncSetAttribute(trms<__half>, cudaFuncAttributeMaxDynamicSharedMemorySize, TRMS_SMEM);
        cudaStreamCreateWithFlags(&s1, cudaStreamNonBlocking);
        cudaEventCreateWithFlags(&evFork, cudaEventDisableTiming);
        cudaEventCreateWithFlags(&evW,    cudaEventDisableTiming);
        cudaEventCreateWithFlags(&evH,    cudaEventDisableTiming);
        cudaEventCreateWithFlags(&evQK,   cudaEventDisableTiming);
        cudaEventCreateWithFlags(&evV,    cudaEventDisableTiming);
        cudaEventCreateWithFlags(&evQ1,   cudaEventDisableTiming);
        cudaEventCreateWithFlags(&evQ2,   cudaEventDisableTiming);
        cudaEventCreateWithFlags(&evEnd,  cudaEventDisableTiming);
        attr_set = 1;
    }

    const float scale = 0.04419417382415922f;   // 512^-0.5
    const long ZB   = 1024L * 512;              // O/X1 per-t row-block stride (ld 512)
    const long ZQK  = 1024L * 1024;             // QK per-t stride (ld 1024)
    const long ZS   = 1L << 20;                 // S/P per-t stride
    const long WS   = 512L * 512;

    // ---- fork: convw on s1, trms on main stream ----
    cudaEventRecord(evFork, 0);
    cudaStreamWaitEvent(s1, evFork, 0);

    convw<<<8192, 256, 0, s1>>>(qs_w, ks_w, vs_w, ps_w, qt_w, kt_w, vt_w, pt_w,
                                qs_b, ks_b, qt_b, kt_b, vt_b, W, BC);
    cudaEventRecord(evW, s1);

    trms<float><<<512, 256, TRMS_SMEM>>>(x, H, gm_s, 0);
    cudaEventRecord(evH, 0);

    // ---- spatial ----
    // s0: QK GEMM (needs W)
    cudaStreamWaitEvent(0, evW, 0);
    gemm_h<true,0><<<dim3(8, 128, 1), 256, GDSMEM>>>(H, 512, 0,  W, 512, 0,
        QKV, 1024, 0, BC, 0, nullptr, 512, 1.f);
    cudaEventRecord(evQK, 0);

    // s1: V GEMM in parallel (has W from convw; needs H)
    cudaStreamWaitEvent(s1, evH, 0);
    gemm_h<true,0><<<dim3(128, 4, 1), 256, GDSMEM, s1>>>(W + 2*WS, 512, 0,  H, 512, 0,
        V, NPOS, 0, vs_b, 1, nullptr, 512, 1.f);
    cudaEventRecord(evV, s1);

    // ---- attention middle + spatial epilogue, z-split across streams ----
    // s0: z = 0..7 -> ps_h1 (X1 t=0..7) -> trms_h1 -> tQKV t=0..7 (pure s0 chain)
    gemm_h<true,0><<<dim3(8, 8, 8), 256, GDSMEM>>>(QKV, 1024, ZQK,  QKV + 512, 1024, ZQK,
        S, 1024, ZS, nullptr, 0, nullptr, 512, scale);
    softmax1024h<<<8*1024, 256>>>(S, P);
    cudaStreamWaitEvent(0, evV, 0);
    gemm_h<true,0><<<dim3(4, 8, 8), 256, GDSMEM>>>(P, 1024, ZS,  V, NPOS, 1024,
        O, 512, ZB, nullptr, 0, nullptr, 1024, 1.f);
    gemm_h<true,1><<<dim3(64, 4, 1), 256, GDSMEM>>>(W + 3*WS, 512, 0,  O, 512, 0,
        X1, NPOS, 0, ps_b, 1, x, 512, 1.f);
    trms<__half><<<256, 256, TRMS_SMEM>>>(X1, H, gm_t, 0);
    // tQKV t=0..7: A = H rows 0..8191, C = QKV rows 0..8191 (ld 1536)
    gemm_h<true,0><<<dim3(12, 64, 1), 256, GDSMEM>>>(H, 512, 0,  W + 4*WS, 512, 0,
        QKV, 1536, 0, BC + 2048, 0, nullptr, 512, 1.f);
    cudaEventRecord(evQ1, 0);

    // s1: z = 8..15 -> ps_h2 (X1 t=8..15) -> trms_h2 -> tQKV t=8..15 (pure s1 chain)
    cudaStreamWaitEvent(s1, evQK, 0);
    gemm_h<true,0><<<dim3(8, 8, 8), 256, GDSMEM, s1>>>(QKV + 8*ZQK, 1024, ZQK,
        QKV + 512 + 8*ZQK, 1024, ZQK,
        S + 8*ZS, 1024, ZS, nullptr, 0, nullptr, 512, scale);
    softmax1024h<<<8*1024, 256, 0, s1>>>(S + 8*ZS, P + 8*ZS);
    gemm_h<true,0><<<dim3(4, 8, 8), 256, GDSMEM, s1>>>(P + 8*ZS, 1024, ZS,  V + 8*1024, NPOS, 1024,
        O + 8*ZB, 512, ZB, nullptr, 0, nullptr, 1024, 1.f);
    gemm_h<true,1><<<dim3(64, 4, 1), 256, GDSMEM, s1>>>(W + 3*WS, 512, 0,  O + 8*ZB, 512, 0,
        X1 + 8192, NPOS, 0, ps_b, 1, x + 8192, 512, 1.f);
    trms<__half><<<256, 256, TRMS_SMEM, s1>>>(X1, H, gm_t, 8192);
    gemm_h<true,0><<<dim3(12, 64, 1), 256, GDSMEM, s1>>>(H + 8192L*512, 512, 0,  W + 4*WS, 512, 0,
        QKV + 8192L*1536, 1536, 0, BC + 2048, 0, nullptr, 512, 1.f);
    cudaEventRecord(evQ2, s1);

    // ---- temporal attention + output, hw-split; join here (small kernels) ----
    // s0: hw < 512 (needs both tQKV halves)
    cudaStreamWaitEvent(0, evQ2, 0);
    temporal_t<<<512, 128>>>(QKV, O, winp, 0);
    gemm_h<false,2><<<dim3(4, 4, 16), 256, GDSMEM>>>(W + 7*WS, 512, 0,  O, 512, ZB,
        out, NPOS, 1024, pt_b, 1, X1, 512, 1.f);

    // s1: hw >= 512
    cudaStreamWaitEvent(s1, evQ1, 0);
    temporal_t<<<512, 128, 0, s1>>>(QKV, O, winp, 512);
    gemm_h<false,2><<<dim3(4, 4, 16), 256, GDSMEM, s1>>>(W + 7*WS, 512, 0,  O + 512*512, 512, ZB,
        out + 512, NPOS, 1024, pt_b, 1, X1 + 512, 512, 1.f);
    cudaEventRecord(evEnd, s1);

    // join s1 back into the capture-origin stream
    cudaStreamWaitEvent(0, evEnd, 0);
}

// round 17
// speedup vs baseline: 1.0626x; 1.0626x over previous
#include <cuda_runtime.h>
#include <cuda_fp16.h>
#include <cstdint>
#include <math.h>

#define CDIM 512
#define NPOS 16384   // T*H*W
#define NELEM (CDIM*NPOS)

// ------------------------- scratch (device globals) -------------------------
__device__ __half g_X1[NELEM];            // fp16 residual carrier [c,n] after spatial
__device__ __half g_S [16*1024*1024];     // fp16 scores
__device__ __half g_H  [NELEM];           // rms output [n,c]
__device__ __half g_QKV[NPOS*1536];       // spatial QK (ld 1024) / temporal QKV (ld 1536)
__device__ __half g_V [NELEM];            // spatial V [c,n]
__device__ __half g_O [NELEM];            // attention out [n,c]
__device__ __half g_P [16*1024*1024];     // fp16 attention probs
__device__ __half g_W [8*CDIM*CDIM];      // fp16 weights (qs ks vs ps qt kt vt pt)
__device__ float  g_BC[4096];             // packed biases

// ------------------------- helpers -------------------------
__device__ __forceinline__ uint32_t smem_u32(const void* p){
    uint32_t a;
    asm("{ .reg .u64 t; cvta.to.shared.u64 t, %1; cvt.u32.u64 %0, t; }" : "=r"(a) : "l"(p));
    return a;
}
#define CP_ASYNC16(dst_u32, src_ptr) \
    asm volatile("cp.async.cg.shared.global [%0], [%1], 16;" :: "r"(dst_u32), "l"(src_ptr))
#define CP_COMMIT() asm volatile("cp.async.commit_group;" ::: "memory")
#define CP_WAIT0()  asm volatile("cp.async.wait_group 0;" ::: "memory")
#define CP_WAIT1()  asm volatile("cp.async.wait_group 1;" ::: "memory")

__device__ __forceinline__ void mma_f16(float* d, const uint32_t* a, const uint32_t* b){
    asm volatile(
        "mma.sync.aligned.m16n8k16.row.col.f32.f16.f16.f32 "
        "{%0,%1,%2,%3}, {%4,%5,%6,%7}, {%8,%9}, {%0,%1,%2,%3};"
        : "+f"(d[0]), "+f"(d[1]), "+f"(d[2]), "+f"(d[3])
        : "r"(a[0]), "r"(a[1]), "r"(a[2]), "r"(a[3]), "r"(b[0]), "r"(b[1]));
}
__device__ __forceinline__ void ldm_x4(uint32_t* r, uint32_t addr){
    asm volatile("ldmatrix.sync.aligned.m8n8.x4.shared.b16 {%0,%1,%2,%3}, [%4];"
        : "=r"(r[0]), "=r"(r[1]), "=r"(r[2]), "=r"(r[3]) : "r"(addr));
}

// ---------------------------------------------------------------------------
// fp16 mma.sync GEMM (best config), both operands K-major:
//   C[z*czs + (y*128+r)*ldc + x*128 + s] =
//     scale * sum_k A[...] * B[...]  (+ bias[row or col])  (+ Res)
// OUTH: write fp16 (else fp32). RESM: 0 none, 1 fp32 residual, 2 fp16 residual.
// Block 128x128, BK=64, 256 threads (2x4 warps), 3-stage cp.async, 2 CTAs/SM.
// ---------------------------------------------------------------------------
#define BK     64
#define ROWB   144                   // 64 halfs (128B) + 16B pad
#define STAGEB (128*ROWB*2)          // A+B per stage = 36864 B
#define GDSMEM (STAGEB*3)            // 110592 B

template<bool OUTH, int RESM>
__global__ void __launch_bounds__(256, 2)
gemm_h(const __half* __restrict__ A, long lda, long azs,
       const __half* __restrict__ B, long ldb, long bzs,
       void* __restrict__ Cp, long ldc, long czs,
       const float* __restrict__ bias, int biasRow,
       const void* __restrict__ Res,
       int Kdim, float scale)
{
    extern __shared__ char sm[];
    const int tid  = threadIdx.x;
    const int wid  = tid >> 5;
    const int lane = tid & 31;
    const int wm   = wid >> 2;   // 0..1 (m half: 64 rows)
    const int wn   = wid & 3;    // 0..3 (n quarter: 32 cols)

    const long mRow0 = (long)blockIdx.y * 128;
    const long nCol0 = (long)blockIdx.x * 128;
    const __half* Ag = A + (long)blockIdx.z * azs + mRow0 * lda;
    const __half* Bg = B + (long)blockIdx.z * bzs + nCol0 * ldb;

    const uint32_t sbase = smem_u32(sm);
    const int lrow = tid >> 3;        // 0..31
    const int loct = tid & 7;         // 16B octant within 128B row

    const uint32_t lmOff = (uint32_t)(lane & 15) * ROWB + (uint32_t)(lane >> 4) * 16;

    float acc[4][4][4];
    #pragma unroll
    for (int i = 0; i < 4; i++)
        #pragma unroll
        for (int j = 0; j < 4; j++)
            #pragma unroll
            for (int q = 0; q < 4; q++) acc[i][j][q] = 0.f;

    const int NC = Kdim >> 6;   // BK = 64

    #define LOADC(cc, st) do {                                                    \
        const long k0 = (long)(cc) * BK;                                          \
        uint32_t dA = sbase + (st)*STAGEB;                                        \
        uint32_t dB = dA + 128*ROWB;                                              \
        _Pragma("unroll")                                                         \
        for (int i = 0; i < 4; i++) {                                             \
            int row = lrow + i*32;                                                \
            CP_ASYNC16(dA + row*ROWB + loct*16, Ag + (long)row*lda + k0 + loct*8);\
            CP_ASYNC16(dB + row*ROWB + loct*16, Bg + (long)row*ldb + k0 + loct*8);\
        }                                                                         \
        CP_COMMIT();                                                               \
    } while(0)

    LOADC(0, 0); LOADC(1, 1);

    int st = 0;
    for (int c = 0; c < NC; ++c) {
        if (c + 1 < NC) CP_WAIT1(); else CP_WAIT0();
        __syncthreads();
        if (c + 2 < NC) {
            int st2 = st + 2; if (st2 >= 3) st2 -= 3;
            LOADC(c + 2, st2);
        }

        const uint32_t stB = sbase + st*STAGEB;
        const uint32_t aAddr = stB + (uint32_t)(wm*64)*ROWB + lmOff;
        const uint32_t bAddr = stB + 128*ROWB + (uint32_t)(wn*32)*ROWB + lmOff;

        #pragma unroll
        for (int ks = 0; ks < 4; ks++) {
            const uint32_t kOff = ks*32;
            uint32_t af[4][4];
            #pragma unroll
            for (int mi = 0; mi < 4; mi++)
                ldm_x4(af[mi], aAddr + mi*(16*ROWB) + kOff);
            uint32_t bf[4][2];
            #pragma unroll
            for (int g = 0; g < 2; g++) {
                uint32_t bq4[4];
                ldm_x4(bq4, bAddr + g*(16*ROWB) + kOff);
                bf[2*g+0][0] = bq4[0]; bf[2*g+1][0] = bq4[1];
                bf[2*g+0][1] = bq4[2]; bf[2*g+1][1] = bq4[3];
            }
            #pragma unroll
            for (int mi = 0; mi < 4; mi++)
                #pragma unroll
                for (int ni = 0; ni < 4; ni++)
                    mma_f16(acc[mi][ni], af[mi], bf[ni]);
        }

        if (++st == 3) st = 0;
    }

    // ---- epilogue ----
    const long rBase = mRow0 + wm*64 + (lane >> 2);
    const long cBase = nCol0 + wn*32 + (lane & 3) * 2;
    #pragma unroll
    for (int mi = 0; mi < 4; mi++) {
        #pragma unroll
        for (int half_ = 0; half_ < 2; half_++) {
            const long r = rBase + mi*16 + half_*8;
            const float bvr = (bias && biasRow) ? __ldg(bias + r) : 0.f;
            const long rowOff = (long)blockIdx.z * czs + r * ldc;
            #pragma unroll
            for (int ni = 0; ni < 4; ni++) {
                const long cc = cBase + ni*8;
                float v0 = acc[mi][ni][half_*2 + 0] * scale;
                float v1 = acc[mi][ni][half_*2 + 1] * scale;
                if (bias) {
                    if (biasRow) { v0 += bvr; v1 += bvr; }
                    else { v0 += __ldg(bias + cc); v1 += __ldg(bias + cc + 1); }
                }
                if (RESM == 1) {
                    float2 rv = *reinterpret_cast<const float2*>(
                        (const float*)Res + rowOff + cc);
                    v0 += rv.x; v1 += rv.y;
                } else if (RESM == 2) {
                    __half2 rh = *reinterpret_cast<const __half2*>(
                        (const __half*)Res + rowOff + cc);
                    float2 rf = __half22float2(rh);
                    v0 += rf.x; v1 += rf.y;
                }
                if (OUTH) {
                    __half2 h = __floats2half2_rn(v0, v1);
                    *reinterpret_cast<__half2*>((__half*)Cp + rowOff + cc) = h;
                } else {
                    float2 o; o.x = v0; o.y = v1;
                    *reinterpret_cast<float2*>((float*)Cp + rowOff + cc) = o;
                }
            }
        }
    }
    #undef LOADC
}

// ---------------------------------------------------------------------------
// Weight fp32->fp16 conversion + bias packing
// ---------------------------------------------------------------------------
__global__ void convw(const float* __restrict__ w0, const float* __restrict__ w1,
                      const float* __restrict__ w2, const float* __restrict__ w3,
                      const float* __restrict__ w4, const float* __restrict__ w5,
                      const float* __restrict__ w6, const float* __restrict__ w7,
                      const float* __restrict__ qsb, const float* __restrict__ ksb,
                      const float* __restrict__ qtb, const float* __restrict__ ktb,
                      const float* __restrict__ vtb,
                      __half* __restrict__ W, float* __restrict__ BC)
{
    long i = (long)blockIdx.x * 256 + threadIdx.x;
    int sel = (int)(i >> 18);
    long off = i & 262143;
    const float* src;
    switch (sel) {
        case 0: src = w0; break; case 1: src = w1; break;
        case 2: src = w2; break; case 3: src = w3; break;
        case 4: src = w4; break; case 5: src = w5; break;
        case 6: src = w6; break; default: src = w7; break;
    }
    W[i] = __float2half_rn(src[off]);
    if (i < 2560) {
        long j = i;
        if      (j < 512)  BC[j]               = qsb[j];
        else if (j < 1024) BC[j]               = ksb[j - 512];
        else if (j < 1536) BC[2048 + (j-1024)] = qtb[j - 1024];
        else if (j < 2048) BC[2560 + (j-1536)] = ktb[j - 1536];
        else               BC[3072 + (j-2048)] = vtb[j - 2048];
    }
}

// ---------------------------------------------------------------------------
// Fused transpose + RMS: X [c,n] (fp32 or fp16) -> H [n,c] fp16
// Handles positions [nbase + blockIdx.x*32, +32).
// ---------------------------------------------------------------------------
#define TRMS_SMEM (512*33*4)
template<typename TI>
__global__ void __launch_bounds__(256)
trms(const TI* __restrict__ X, __half* __restrict__ H,
     const float* __restrict__ gamma, int nbase)
{
    extern __shared__ float ts[];   // [512][33]
    __shared__ float red[8][32];
    __shared__ float invs[32];
    const int n0 = nbase + blockIdx.x * 32;
    const int tid = threadIdx.x;

    if (sizeof(TI) == 4) {
        for (int idx = tid; idx < 4096; idx += 256) {
            int c = idx >> 3, q = idx & 7;
            float4 v = *reinterpret_cast<const float4*>((const float*)X + (long)c*NPOS + n0 + q*4);
            float* row = ts + c*33 + q*4;
            row[0]=v.x; row[1]=v.y; row[2]=v.z; row[3]=v.w;
        }
    } else {
        for (int idx = tid; idx < 2048; idx += 256) {
            int c = idx >> 2, q = idx & 3;
            uint4 u = *reinterpret_cast<const uint4*>((const __half*)X + (long)c*NPOS + n0 + q*8);
            const __half* hp = reinterpret_cast<const __half*>(&u);
            float* row = ts + c*33 + q*8;
            #pragma unroll
            for (int j = 0; j < 8; j++) row[j] = __half2float(hp[j]);
        }
    }
    __syncthreads();
    {
        int col = tid & 31, seg = tid >> 5;
        float ss = 0.f;
        #pragma unroll 8
        for (int c = seg*64; c < seg*64 + 64; c++) {
            float v = ts[c*33 + col]; ss += v*v;
        }
        red[seg][col] = ss;
    }
    __syncthreads();
    if (tid < 32) {
        float ss = 0.f;
        #pragma unroll
        for (int s = 0; s < 8; s++) ss += red[s][tid];
        invs[tid] = 22.62741699796952f / fmaxf(sqrtf(ss), 1e-12f);
    }
    __syncthreads();
    for (int idx = tid; idx < 16384; idx += 256) {
        int nl = idx >> 9, c = idx & 511;
        float v = ts[c*33 + nl];
        H[(long)(n0 + nl) * 512 + c] = __float2half_rn(v * invs[nl] * gamma[c]);
    }
}

// ---------------------------------------------------------------------------
// Softmax over 1024-long fp16 rows -> fp16 probs
// ---------------------------------------------------------------------------
__global__ void softmax1024h(const __half* __restrict__ S, __half* __restrict__ P)
{
    size_t row = blockIdx.x;
    const uint2* p = reinterpret_cast<const uint2*>(S + row * 1024);
    int tid = threadIdx.x;
    uint2 u = p[tid];
    float2 a = __half22float2(*reinterpret_cast<__half2*>(&u.x));
    float2 b = __half22float2(*reinterpret_cast<__half2*>(&u.y));
    float4 v; v.x = a.x; v.y = a.y; v.z = b.x; v.w = b.y;

    __shared__ float redm[8];
    __shared__ float reds[8];

    float mx = fmaxf(fmaxf(v.x, v.y), fmaxf(v.z, v.w));
    #pragma unroll
    for (int o = 16; o; o >>= 1) mx = fmaxf(mx, __shfl_xor_sync(0xffffffffu, mx, o));
    if ((tid & 31) == 0) redm[tid >> 5] = mx;
    __syncthreads();
    mx = redm[0];
    #pragma unroll
    for (int i = 1; i < 8; i++) mx = fmaxf(mx, redm[i]);

    v.x = __expf(v.x - mx); v.y = __expf(v.y - mx);
    v.z = __expf(v.z - mx); v.w = __expf(v.w - mx);

    float sm = v.x + v.y + v.z + v.w;
    #pragma unroll
    for (int o = 16; o; o >>= 1) sm += __shfl_xor_sync(0xffffffffu, sm, o);
    if ((tid & 31) == 0) reds[tid >> 5] = sm;
    __syncthreads();
    sm = 0.f;
    #pragma unroll
    for (int i = 0; i < 8; i++) sm += reds[i];

    float r = 1.f / sm;
    __half2 h0 = __floats2half2_rn(v.x * r, v.y * r);
    __half2 h1 = __floats2half2_rn(v.z * r, v.w * r);
    __half2* dst = reinterpret_cast<__half2*>(P + row * 1024 + tid * 4);
    dst[0] = h0; dst[1] = h1;
}

// ---------------------------------------------------------------------------
// Temporal attention: QKV packed [NPOS, 1536] fp16 (Q +0, K +512, V +1024).
// Block = one hw (hw0 + blockIdx.x), 128 threads. O out [NPOS, 512] fp16.
// ---------------------------------------------------------------------------
__global__ void __launch_bounds__(128)
temporal_t(const __half* __restrict__ QKV, __half* __restrict__ Ot,
           const int* __restrict__ winp, int hw0)
{
    __shared__ float kv[16][512];
    __shared__ float at[16][16];
    const int hw = hw0 + blockIdx.x;
    const int tid = threadIdx.x;
    const int wid = tid >> 5, lane = tid & 31;
    const float scale = 0.04419417382415922f;

    for (int idx = tid; idx < 4096; idx += 128) {
        int t = idx >> 8, c2 = idx & 255;
        __half2 h = *reinterpret_cast<const __half2*>(QKV + ((long)(t*1024 + hw))*1536 + 512 + c2*2);
        float2 f = __half22float2(h);
        kv[t][c2*2] = f.x; kv[t][c2*2+1] = f.y;
    }
    __syncthreads();

    #pragma unroll
    for (int ii = 0; ii < 4; ii++) {
        int i = wid + ii*4;
        float qv[16];
        const __half* qr = QKV + ((long)(i*1024 + hw)) * 1536;
        #pragma unroll
        for (int u = 0; u < 16; u++) qv[u] = __half2float(qr[lane + 32*u]);
        #pragma unroll
        for (int j = 0; j < 16; j++) {
            float s = 0.f;
            #pragma unroll
            for (int u = 0; u < 16; u++) s += qv[u] * kv[j][lane + 32*u];
            #pragma unroll
            for (int o = 16; o; o >>= 1) s += __shfl_xor_sync(0xffffffffu, s, o);
            if (lane == 0) at[i][j] = s * scale;
        }
    }
    __syncthreads();

    int win = winp ? *winp : 8;
    if (tid < 16) {
        int i = tid;
        float mx = -3.0e38f;
        #pragma unroll
        for (int j = 0; j < 16; j++) {
            bool ok = (j <= i) && (win <= 0 || (i - j) < win);
            if (ok) mx = fmaxf(mx, at[i][j]);
        }
        float sum = 0.f, e[16];
        #pragma unroll
        for (int j = 0; j < 16; j++) {
            bool ok = (j <= i) && (win <= 0 || (i - j) < win);
            e[j] = ok ? __expf(at[i][j] - mx) : 0.f;
            sum += e[j];
        }
        float rinv = 1.f / sum;
        #pragma unroll
        for (int j = 0; j < 16; j++) at[i][j] = e[j] * rinv;
    }
    __syncthreads();

    for (int idx = tid; idx < 4096; idx += 128) {
        int t = idx >> 8, c2 = idx & 255;
        __half2 h = *reinterpret_cast<const __half2*>(QKV + ((long)(t*1024 + hw))*1536 + 1024 + c2*2);
        float2 f = __half22float2(h);
        kv[t][c2*2] = f.x; kv[t][c2*2+1] = f.y;
    }
    __syncthreads();

    #pragma unroll
    for (int ii = 0; ii < 4; ii++) {
        int i = wid + ii*4;
        float a[16];
        #pragma unroll
        for (int j = 0; j < 16; j++) a[j] = at[i][j];
        __half* orow = Ot + ((long)(i*1024 + hw)) * 512;
        #pragma unroll
        for (int u = 0; u < 16; u++) {
            float o = 0.f;
            #pragma unroll
            for (int j = 0; j < 16; j++) o += a[j] * kv[j][lane + 32*u];
            orow[lane + 32*u] = __float2half_rn(o);
        }
    }
}

// ---------------------------------------------------------------------------
extern "C" void kernel_launch(void* const* d_in, const int* in_sizes, int n_in,
                              void* d_out, int out_size)
{
    const float* x     = (const float*)d_in[0];
    const float* qs_w  = (const float*)d_in[1];
    const float* qs_b  = (const float*)d_in[2];
    const float* ks_w  = (const float*)d_in[3];
    const float* ks_b  = (const float*)d_in[4];
    const float* vs_w  = (const float*)d_in[5];
    const float* vs_b  = (const float*)d_in[6];
    const float* ps_w  = (const float*)d_in[7];
    const float* ps_b  = (const float*)d_in[8];
    const float* qt_w  = (const float*)d_in[9];
    const float* qt_b  = (const float*)d_in[10];
    const float* kt_w  = (const float*)d_in[11];
    const float* kt_b  = (const float*)d_in[12];
    const float* vt_w  = (const float*)d_in[13];
    const float* vt_b  = (const float*)d_in[14];
    const float* pt_w  = (const float*)d_in[15];
    const float* pt_b  = (const float*)d_in[16];
    const float* gm_s  = (const float*)d_in[17];
    const float* gm_t  = (const float*)d_in[18];
    const int*   winp  = (n_in > 19) ? (const int*)d_in[19] : nullptr;
    float* out = (float*)d_out;

    float *BC;
    __half *X1, *S, *H, *QKV, *V, *O, *P, *W;
    cudaGetSymbolAddress((void**)&X1,  g_X1);
    cudaGetSymbolAddress((void**)&S,   g_S);
    cudaGetSymbolAddress((void**)&BC,  g_BC);
    cudaGetSymbolAddress((void**)&H,   g_H);
    cudaGetSymbolAddress((void**)&QKV, g_QKV);
    cudaGetSymbolAddress((void**)&V,   g_V);
    cudaGetSymbolAddress((void**)&O,   g_O);
    cudaGetSymbolAddress((void**)&P,   g_P);
    cudaGetSymbolAddress((void**)&W,   g_W);

    static int attr_set = 0;
    static cudaStream_t s1;
    static cudaEvent_t evFork, evW, evT1, evT2, evEnd;
    if (!attr_set) {
        cudaFuncSetAttribute(gemm_h<true,0>,  cudaFuncAttributeMaxDynamicSharedMemorySize, GDSMEM);
        cudaFuncSetAttribute(gemm_h<true,1>,  cudaFuncAttributeMaxDynamicSharedMemorySize, GDSMEM);
        cudaFuncSetAttribute(gemm_h<false,2>, cudaFuncAttributeMaxDynamicSharedMemorySize, GDSMEM);
        cudaFuncSetAttribute(trms<float>,  cudaFuncAttributeMaxDynamicSharedMemorySize, TRMS_SMEM);
        cudaFuncSetAttribute(trms<__half>, cudaFuncAttributeMaxDynamicSharedMemorySize, TRMS_SMEM);
        cudaStreamCreateWithFlags(&s1, cudaStreamNonBlocking);
        cudaEventCreateWithFlags(&evFork, cudaEventDisableTiming);
        cudaEventCreateWithFlags(&evW,    cudaEventDisableTiming);
        cudaEventCreateWithFlags(&evT1,   cudaEventDisableTiming);
        cudaEventCreateWithFlags(&evT2,   cudaEventDisableTiming);
        cudaEventCreateWithFlags(&evEnd,  cudaEventDisableTiming);
        attr_set = 1;
    }

    const float scale = 0.04419417382415922f;   // 512^-0.5
    const long ZB   = 1024L * 512;              // O/X1 per-t row-block stride (ld 512)
    const long ZQK  = 1024L * 1024;             // QK per-t stride (ld 1024)
    const long ZS   = 1L << 20;                 // S/P per-t stride
    const long WS   = 512L * 512;
    const long ZT   = 1024L * 1536;             // tQKV output per-t stride (ld 1536)
    const long HHW  = 512L * 512;               // hw-half offset in [n,c] rows

    cudaEventRecord(evFork, 0);
    cudaStreamWaitEvent(s1, evFork, 0);

    // ================= LANE s1 (t = 8..15) =================
    convw<<<8192, 256, 0, s1>>>(qs_w, ks_w, vs_w, ps_w, qt_w, kt_w, vt_w, pt_w,
                                qs_b, ks_b, qt_b, kt_b, vt_b, W, BC);
    cudaEventRecord(evW, s1);
    trms<float><<<256, 256, TRMS_SMEM, s1>>>(x, H, gm_s, 8192);
    // QK_h2: rows 8192..16383
    gemm_h<true,0><<<dim3(8, 64, 1), 256, GDSMEM, s1>>>(H + 8192L*512, 512, 0,  W, 512, 0,
        QKV + 8192L*1024, 1024, 0, BC, 0, nullptr, 512, 1.f);
    // V_h2: cols 8192..16383
    gemm_h<true,0><<<dim3(64, 4, 1), 256, GDSMEM, s1>>>(W + 2*WS, 512, 0,  H + 8192L*512, 512, 0,
        V + 8192, NPOS, 0, vs_b, 1, nullptr, 512, 1.f);
    // scores z=8..15
    gemm_h<true,0><<<dim3(8, 8, 8), 256, GDSMEM, s1>>>(QKV + 8*ZQK, 1024, ZQK,
        QKV + 512 + 8*ZQK, 1024, ZQK,
        S + 8*ZS, 1024, ZS, nullptr, 0, nullptr, 512, scale);
    softmax1024h<<<8*1024, 256, 0, s1>>>(S + 8*ZS, P + 8*ZS);
    gemm_h<true,0><<<dim3(4, 8, 8), 256, GDSMEM, s1>>>(P + 8*ZS, 1024, ZS,  V + 8*1024, NPOS, 1024,
        O + 8*ZB, 512, ZB, nullptr, 0, nullptr, 1024, 1.f);
    // ps_h2: X1 cols 8192..16383
    gemm_h<true,1><<<dim3(64, 4, 1), 256, GDSMEM, s1>>>(W + 3*WS, 512, 0,  O + 8*ZB, 512, 0,
        X1 + 8192, NPOS, 0, ps_b, 1, x + 8192, 512, 1.f);
    trms<__half><<<256, 256, TRMS_SMEM, s1>>>(X1, H, gm_t, 8192);
    cudaEventRecord(evT2, s1);

    // ================= LANE s0 (t = 0..7) =================
    trms<float><<<256, 256, TRMS_SMEM>>>(x, H, gm_s, 0);
    cudaStreamWaitEvent(0, evW, 0);
    // QK_h1: rows 0..8191
    gemm_h<true,0><<<dim3(8, 64, 1), 256, GDSMEM>>>(H, 512, 0,  W, 512, 0,
        QKV, 1024, 0, BC, 0, nullptr, 512, 1.f);
    // V_h1: cols 0..8191
    gemm_h<true,0><<<dim3(64, 4, 1), 256, GDSMEM>>>(W + 2*WS, 512, 0,  H, 512, 0,
        V, NPOS, 0, vs_b, 1, nullptr, 512, 1.f);
    // scores z=0..7
    gemm_h<true,0><<<dim3(8, 8, 8), 256, GDSMEM>>>(QKV, 1024, ZQK,  QKV + 512, 1024, ZQK,
        S, 1024, ZS, nullptr, 0, nullptr, 512, scale);
    softmax1024h<<<8*1024, 256>>>(S, P);
    gemm_h<true,0><<<dim3(4, 8, 8), 256, GDSMEM>>>(P, 1024, ZS,  V, NPOS, 1024,
        O, 512, ZB, nullptr, 0, nullptr, 1024, 1.f);
    // ps_h1: X1 cols 0..8191
    gemm_h<true,1><<<dim3(64, 4, 1), 256, GDSMEM>>>(W + 3*WS, 512, 0,  O, 512, 0,
        X1, NPOS, 0, ps_b, 1, x, 512, 1.f);
    trms<__half><<<256, 256, TRMS_SMEM>>>(X1, H, gm_t, 0);
    cudaEventRecord(evT1, 0);

    // ---- temporal, hw-split (R15 back end) ----
    // s0: tQKV hw<512 (needs full H -> wait evT2), temporal hw<512, pt_h1
    cudaStreamWaitEvent(0, evT2, 0);
    gemm_h<true,0><<<dim3(12, 4, 16), 256, GDSMEM>>>(H, 512, ZB,  W + 4*WS, 512, 0,
        QKV, 1536, ZT, BC + 2048, 0, nullptr, 512, 1.f);
    temporal_t<<<512, 128>>>(QKV, O, winp, 0);
    gemm_h<false,2><<<dim3(4, 4, 16), 256, GDSMEM>>>(W + 7*WS, 512, 0,  O, 512, ZB,
        out, NPOS, 1024, pt_b, 1, X1, 512, 1.f);

    // s1: tQKV hw>=512 (wait evT1), temporal hw>=512, pt_h2
    cudaStreamWaitEvent(s1, evT1, 0);
    gemm_h<true,0><<<dim3(12, 4, 16), 256, GDSMEM, s1>>>(H + HHW, 512, ZB,  W + 4*WS, 512, 0,
        QKV + 512*1536, 1536, ZT, BC + 2048, 0, nullptr, 512, 1.f);
    temporal_t<<<512, 128, 0, s1>>>(QKV, O, winp, 512);
    gemm_h<false,2><<<dim3(4, 4, 16), 256, GDSMEM, s1>>>(W + 7*WS, 512, 0,  O + 512*512, 512, ZB,
        out + 512, NPOS, 1024, pt_b, 1, X1 + 512, 512, 1.f);
    cudaEventRecord(evEnd, s1);

    // join s1 back into the capture-origin stream
    cudaStreamWaitEvent(0, evEnd, 0);
}